// round 1
// baseline (speedup 1.0000x reference)
#include <cuda_runtime.h>
#include <cstdint>

#define N_NODES 100000
#define IN_F    32
#define OUT_F   64
#define K_TOT   25
#define KDIM    800   /* 25 * 32 flattened K dimension */
#define TILE_M  64

// 320 MB scratch accumulator. Zero-initialized at module load; the GEMM kernel
// re-zeroes every chunk it consumes, so each kernel_launch call starts clean.
__device__ __align__(16) float g_H[(size_t)N_NODES * KDIM];

// ---------------------------------------------------------------------------
// Phase 1: edge scatter.  One warp handles 32 edges: coalesced loads of
// edge metadata, then per-edge broadcast via shuffles; each corner update is
// one coalesced 32-lane RED.ADD.F32 covering a full 128B line of H.
// ---------------------------------------------------------------------------
__global__ void scatter_kernel(const float*  __restrict__ feat,
                               const float2* __restrict__ pseudo,
                               const int*    __restrict__ ei,
                               int E) {
    float* __restrict__ H = g_H;
    const int lane = threadIdx.x & 31;
    const int warp_global = (int)((blockIdx.x * blockDim.x + threadIdx.x) >> 5);
    const int base = warp_global * 32;
    if (base >= E) return;

    const int e = base + lane;
    int col = 0, hb = 0;
    float b00 = 0.f, b01 = 0.f, b10 = 0.f, b11 = 0.f;
    if (e < E) {
        int row = ei[e];
        col = ei[E + e];
        float2 p = pseudo[e];
        float v0 = p.x * 4.0f;
        float v1 = p.y * 4.0f;
        int i0 = (int)floorf(v0); i0 = i0 < 0 ? 0 : (i0 > 3 ? 3 : i0);
        int i1 = (int)floorf(v1); i1 = i1 < 0 ? 0 : (i1 > 3 ? 3 : i1);
        float f0 = v0 - (float)i0;
        float f1 = v1 - (float)i1;
        float g0 = 1.0f - f0, g1 = 1.0f - f1;
        b00 = g0 * g1; b01 = g0 * f1; b10 = f0 * g1; b11 = f0 * f1;
        hb = (row * K_TOT + i0 * 5 + i1) * IN_F;   // flat offset of corner (0,0)
    }

    int cnt = E - base; if (cnt > 32) cnt = 32;
    for (int j = 0; j < cnt; j++) {
        int   c   = __shfl_sync(0xffffffffu, col, j);
        int   hbj = __shfl_sync(0xffffffffu, hb,  j);
        float w00 = __shfl_sync(0xffffffffu, b00, j);
        float w01 = __shfl_sync(0xffffffffu, b01, j);
        float w10 = __shfl_sync(0xffffffffu, b10, j);
        float w11 = __shfl_sync(0xffffffffu, b11, j);
        float x = __ldg(&feat[c * IN_F + lane]);
        atomicAdd(&H[hbj +            lane], w00 * x);   // corner (0,0)
        atomicAdd(&H[hbj +     IN_F + lane], w01 * x);   // corner (0,1) -> kidx+1
        atomicAdd(&H[hbj + 5 * IN_F + lane], w10 * x);   // corner (1,0) -> kidx+5
        atomicAdd(&H[hbj + 6 * IN_F + lane], w11 * x);   // corner (1,1) -> kidx+6
    }
}

// ---------------------------------------------------------------------------
// Phase 2: out[N,64] = H[N,800] @ W[800,64] + bias, tf32 tensor-core GEMM.
// CTA = 64 rows x 64 cols, 4 warps (each 16x64), K chunked by 32.
// H is consumed-and-cleared: each float4 is loaded then overwritten with
// zeros by the same thread, leaving H clean for the next launch.
// ---------------------------------------------------------------------------
__device__ __forceinline__ uint32_t f2tf32(float f) {
    uint32_t r;
    asm("cvt.rna.tf32.f32 %0, %1;" : "=r"(r) : "f"(f));
    return r;
}

__global__ void __launch_bounds__(128)
gemm_kernel(const float* __restrict__ Wt,    // [800][64] (= weight reshaped)
            const float* __restrict__ bias,  // [64]
            float*       __restrict__ out) { // [N_NODES][64]
    __shared__ uint32_t As[TILE_M][36];  // 64 x 32 tf32, pad 36 (4r+c banks)
    __shared__ uint32_t Bs[32][72];      // 32 x 64 tf32, pad 72 (8k+n banks)
    float* __restrict__ H = g_H;

    const int tid  = threadIdx.x;
    const int lane = tid & 31;
    const int warp = tid >> 5;
    const int row_base = blockIdx.x * TILE_M;

    float acc[8][4];
#pragma unroll
    for (int j = 0; j < 8; j++)
#pragma unroll
        for (int q = 0; q < 4; q++) acc[j][q] = 0.f;

    const int a_r  = lane >> 2;       // 0..7
    const int a_c  = lane & 3;        // 0..3

    for (int kc = 0; kc < 25; kc++) {
        // --- stage A: 64 rows x 32 k  (512 float4, 4 per thread) ---
#pragma unroll
        for (int t = 0; t < 4; t++) {
            int idx = tid + t * 128;          // 0..511
            int r   = idx >> 3;               // row 0..63
            int c4  = idx & 7;                // float4 index 0..7
            int grow = row_base + r;
            float4 v = make_float4(0.f, 0.f, 0.f, 0.f);
            if (grow < N_NODES) {
                float4* p = (float4*)(H + (size_t)grow * KDIM + kc * 32) + c4;
                v = *p;
                *p = make_float4(0.f, 0.f, 0.f, 0.f);   // consume-and-clear
            }
            As[r][c4 * 4 + 0] = f2tf32(v.x);
            As[r][c4 * 4 + 1] = f2tf32(v.y);
            As[r][c4 * 4 + 2] = f2tf32(v.z);
            As[r][c4 * 4 + 3] = f2tf32(v.w);
        }
        // --- stage B: 32 k x 64 cols (512 float4, 4 per thread) ---
#pragma unroll
        for (int t = 0; t < 4; t++) {
            int idx = tid + t * 128;          // 0..511
            int r   = idx >> 4;               // k-row 0..31
            int c4  = idx & 15;               // float4 0..15
            float4 v = *((const float4*)(Wt + (size_t)(kc * 32 + r) * OUT_F) + c4);
            Bs[r][c4 * 4 + 0] = f2tf32(v.x);
            Bs[r][c4 * 4 + 1] = f2tf32(v.y);
            Bs[r][c4 * 4 + 2] = f2tf32(v.z);
            Bs[r][c4 * 4 + 3] = f2tf32(v.w);
        }
        __syncthreads();

#pragma unroll
        for (int ks = 0; ks < 4; ks++) {
            uint32_t a0 = As[warp * 16 + a_r    ][ks * 8 + a_c    ];
            uint32_t a1 = As[warp * 16 + a_r + 8][ks * 8 + a_c    ];
            uint32_t a2 = As[warp * 16 + a_r    ][ks * 8 + a_c + 4];
            uint32_t a3 = As[warp * 16 + a_r + 8][ks * 8 + a_c + 4];
#pragma unroll
            for (int j = 0; j < 8; j++) {
                uint32_t b0 = Bs[ks * 8 + a_c    ][j * 8 + a_r];
                uint32_t b1 = Bs[ks * 8 + a_c + 4][j * 8 + a_r];
                asm volatile(
                    "mma.sync.aligned.m16n8k8.row.col.f32.tf32.tf32.f32 "
                    "{%0,%1,%2,%3}, {%4,%5,%6,%7}, {%8,%9}, {%0,%1,%2,%3};\n"
                    : "+f"(acc[j][0]), "+f"(acc[j][1]),
                      "+f"(acc[j][2]), "+f"(acc[j][3])
                    : "r"(a0), "r"(a1), "r"(a2), "r"(a3), "r"(b0), "r"(b1));
            }
        }
        __syncthreads();
    }

    // --- epilogue: D row r = lane/4 (+8), col = j*8 + (lane%4)*2 (+1) ---
    int r0 = row_base + warp * 16 + a_r;
    int r1 = r0 + 8;
    int cb = a_c * 2;
#pragma unroll
    for (int j = 0; j < 8; j++) {
        int c = j * 8 + cb;
        float bv0 = bias[c], bv1 = bias[c + 1];
        if (r0 < N_NODES) {
            float2* p = (float2*)(out + (size_t)r0 * OUT_F + c);
            *p = make_float2(acc[j][0] + bv0, acc[j][1] + bv1);
        }
        if (r1 < N_NODES) {
            float2* p = (float2*)(out + (size_t)r1 * OUT_F + c);
            *p = make_float2(acc[j][2] + bv0, acc[j][3] + bv1);
        }
    }
}

extern "C" void kernel_launch(void* const* d_in, const int* in_sizes, int n_in,
                              void* d_out, int out_size) {
    const float*  feat   = (const float*) d_in[0];
    const float2* pseudo = (const float2*)d_in[1];
    const int*    ei     = (const int*)   d_in[2];
    const float*  Wt     = (const float*) d_in[3];
    const float*  bias   = (const float*) d_in[4];
    float*        out    = (float*)       d_out;

    const int E = in_sizes[1] / 2;   // pseudo is [E, 2]

    // 8 warps/block, 32 edges per warp -> 256 edges per block
    int sblocks = (E + 255) / 256;
    scatter_kernel<<<sblocks, 256>>>(feat, pseudo, ei, E);

    int gblocks = (N_NODES + TILE_M - 1) / TILE_M;
    gemm_kernel<<<gblocks, 128>>>(Wt, bias, out);
}

// round 2
// speedup vs baseline: 6.6321x; 6.6321x over previous
#include <cuda_runtime.h>
#include <cstdint>

#define N_NODES       100000
#define IN_F          32
#define OUT_F         64
#define K_TOT         25
#define MAX_DEG       96          /* Poisson(16): max over 100K nodes ~36; 96 is ultra-safe */
#define NODES_PER_BLK 32
#define HS_STRIDE     804         /* 800 + 4 pad: (4*a_r + a_c) mod 32 distinct -> conflict-free A reads */
#define THREADS       128

// Per-node edge counters (double as fill cursors) and 16B edge records bucketed by dest node.
__device__ int g_cnt[N_NODES];
__device__ __align__(16) float4 g_rec[(size_t)N_NODES * MAX_DEG];   // ~154 MB static scratch

// ---------------------------------------------------------------------------
__global__ void zero_cnt_kernel() {
    int i = blockIdx.x * blockDim.x + threadIdx.x;
    if (i < N_NODES) g_cnt[i] = 0;
}

// Bucket every edge under its destination node. Order within a node is
// nondeterministic (atomic cursor) but sums are tolerance-checked.
__global__ void bucket_kernel(const int* __restrict__ ei,
                              const float2* __restrict__ ps, int E) {
    int e = blockIdx.x * blockDim.x + threadIdx.x;
    if (e >= E) return;
    int row = ei[e];
    int col = ei[E + e];
    float2 p = ps[e];
    int pos = atomicAdd(&g_cnt[row], 1);
    if (pos < MAX_DEG)
        g_rec[(size_t)row * MAX_DEG + pos] =
            make_float4(__int_as_float(col), p.x, p.y, 0.0f);
}

// ---------------------------------------------------------------------------
__device__ __forceinline__ uint32_t f2tf32(float f) {
    uint32_t r;
    asm("cvt.rna.tf32.f32 %0, %1;" : "=r"(r) : "f"(f));
    return r;
}

// Fused: smem accumulation of H tile (32 nodes x 25*32) + tf32 TC GEMM + bias.
__global__ void __launch_bounds__(THREADS)
fused_kernel(const float* __restrict__ feat,   // [N,32]
             const float* __restrict__ Wt,     // [800][64]
             const float* __restrict__ bias,   // [64]
             float*       __restrict__ out) {  // [N,64]
    extern __shared__ float sm[];
    float*    Hs = sm;                                        // 32 x 804 fp32
    uint32_t* Bs = (uint32_t*)(sm + NODES_PER_BLK * HS_STRIDE); // 32 x 72 tf32

    const int tid   = threadIdx.x;
    const int lane  = tid & 31;
    const int warp  = tid >> 5;
    const int nbase = blockIdx.x * NODES_PER_BLK;

    // --- zero H tile ---
    for (int i = tid; i < NODES_PER_BLK * HS_STRIDE / 4; i += THREADS)
        ((float4*)Hs)[i] = make_float4(0.f, 0.f, 0.f, 0.f);
    __syncthreads();

    // --- accumulation: warp w exclusively owns local nodes [w*8, w*8+8) ---
    for (int ln = warp * 8; ln < warp * 8 + 8; ln++) {
        int n = nbase + ln;
        int c = g_cnt[n];
        if (c > MAX_DEG) c = MAX_DEG;
        if (c == 0) continue;
        const float4* __restrict__ rec = &g_rec[(size_t)n * MAX_DEG];
        float* __restrict__ hrow = Hs + ln * HS_STRIDE;

        // 4-edge chunks, next-chunk records prefetched during current processing
        float4 rc[4];
        float  xv[4];
#pragma unroll
        for (int q = 0; q < 4; q++) { int ii = min(q, c - 1); rc[q] = rec[ii]; }
#pragma unroll
        for (int q = 0; q < 4; q++) {
            int cq = __float_as_int(rc[q].x);
            xv[q] = feat[cq * IN_F + lane];
        }
        for (int base = 0; base < c; base += 4) {
            float4 rn[4];
            const int nb = base + 4;
            if (nb < c) {
#pragma unroll
                for (int q = 0; q < 4; q++) { int ii = min(nb + q, c - 1); rn[q] = rec[ii]; }
            }
#pragma unroll
            for (int q = 0; q < 4; q++) {
                if (base + q < c) {
                    float v0 = rc[q].y * 4.0f;
                    float v1 = rc[q].z * 4.0f;
                    int i0 = (int)v0; i0 = i0 > 3 ? 3 : i0;
                    int i1 = (int)v1; i1 = i1 > 3 ? 3 : i1;
                    float f0 = v0 - (float)i0, f1 = v1 - (float)i1;
                    float g0 = 1.0f - f0,      g1 = 1.0f - f1;
                    int kb = (i0 * 5 + i1) * IN_F + lane;
                    float x = xv[q];
                    hrow[kb             ] += g0 * g1 * x;   // (i0,   i1)
                    hrow[kb +     IN_F  ] += g0 * f1 * x;   // (i0,   i1+1)
                    hrow[kb + 5 * IN_F  ] += f0 * g1 * x;   // (i0+1, i1)
                    hrow[kb + 6 * IN_F  ] += f0 * f1 * x;   // (i0+1, i1+1)
                }
            }
            if (nb < c) {
#pragma unroll
                for (int q = 0; q < 4; q++) {
                    rc[q] = rn[q];
                    int cq = __float_as_int(rc[q].x);
                    xv[q] = feat[cq * IN_F + lane];
                }
            }
        }
    }
    __syncthreads();

    // --- tf32 TC GEMM: out[32,64] = Hs[32,800] @ Wt[800,64] + bias ---
    const int a_r    = lane >> 2;   // 0..7
    const int a_c    = lane & 3;    // 0..3
    const int stripe = warp >> 1;   // 0..1 -> 16-row stripe
    const int nh     = warp & 1;    // 0..1 -> 32-col half

    float acc[4][4];
#pragma unroll
    for (int j = 0; j < 4; j++)
#pragma unroll
        for (int q = 0; q < 4; q++) acc[j][q] = 0.f;

    for (int kc = 0; kc < K_TOT; kc++) {
        // stage W chunk [32 k x 64 n] as tf32 into Bs
#pragma unroll
        for (int t = 0; t < 4; t++) {
            int idx = tid + t * THREADS;     // 0..511
            int r   = idx >> 4;              // k-row 0..31
            int c4  = idx & 15;              // float4 0..15
            float4 v = ((const float4*)(Wt + (size_t)(kc * 32 + r) * OUT_F))[c4];
            uint4 u;
            u.x = f2tf32(v.x); u.y = f2tf32(v.y);
            u.z = f2tf32(v.z); u.w = f2tf32(v.w);
            *(uint4*)(Bs + r * 72 + c4 * 4) = u;
        }
        __syncthreads();

#pragma unroll
        for (int ks = 0; ks < 4; ks++) {
            const float* ab = Hs + (stripe * 16 + a_r) * HS_STRIDE + kc * 32 + ks * 8 + a_c;
            uint32_t a0 = f2tf32(ab[0]);
            uint32_t a1 = f2tf32(ab[8 * HS_STRIDE]);
            uint32_t a2 = f2tf32(ab[4]);
            uint32_t a3 = f2tf32(ab[8 * HS_STRIDE + 4]);
#pragma unroll
            for (int j = 0; j < 4; j++) {
                uint32_t b0 = Bs[(ks * 8 + a_c    ) * 72 + nh * 32 + j * 8 + a_r];
                uint32_t b1 = Bs[(ks * 8 + a_c + 4) * 72 + nh * 32 + j * 8 + a_r];
                asm volatile(
                    "mma.sync.aligned.m16n8k8.row.col.f32.tf32.tf32.f32 "
                    "{%0,%1,%2,%3}, {%4,%5,%6,%7}, {%8,%9}, {%0,%1,%2,%3};\n"
                    : "+f"(acc[j][0]), "+f"(acc[j][1]),
                      "+f"(acc[j][2]), "+f"(acc[j][3])
                    : "r"(a0), "r"(a1), "r"(a2), "r"(a3), "r"(b0), "r"(b1));
            }
        }
        __syncthreads();
    }

    // --- epilogue (N_NODES divisible by 32 -> no row guards) ---
    int r0 = nbase + stripe * 16 + a_r;
    int r1 = r0 + 8;
#pragma unroll
    for (int j = 0; j < 4; j++) {
        int c = nh * 32 + j * 8 + a_c * 2;
        float bv0 = bias[c], bv1 = bias[c + 1];
        *(float2*)(out + (size_t)r0 * OUT_F + c) = make_float2(acc[j][0] + bv0, acc[j][1] + bv1);
        *(float2*)(out + (size_t)r1 * OUT_F + c) = make_float2(acc[j][2] + bv0, acc[j][3] + bv1);
    }
}

// ---------------------------------------------------------------------------
extern "C" void kernel_launch(void* const* d_in, const int* in_sizes, int n_in,
                              void* d_out, int out_size) {
    const float*  feat   = (const float*) d_in[0];
    const float2* pseudo = (const float2*)d_in[1];
    const int*    ei     = (const int*)   d_in[2];
    const float*  Wt     = (const float*) d_in[3];
    const float*  bias   = (const float*) d_in[4];
    float*        out    = (float*)       d_out;

    const int E = in_sizes[1] / 2;

    const int smem_bytes = (NODES_PER_BLK * HS_STRIDE + 32 * 72) * 4;  // 112128
    cudaFuncSetAttribute(fused_kernel, cudaFuncAttributeMaxDynamicSharedMemorySize,
                         smem_bytes);

    zero_cnt_kernel<<<(N_NODES + 255) / 256, 256>>>();
    bucket_kernel<<<(E + 255) / 256, 256>>>(ei, pseudo, E);
    fused_kernel<<<N_NODES / NODES_PER_BLK, THREADS, smem_bytes>>>(feat, Wt, bias, out);
}

// round 3
// speedup vs baseline: 12.6840x; 1.9125x over previous
#include <cuda_runtime.h>
#include <cstdint>

#define N_NODES       100000
#define IN_F          32
#define OUT_F         64
#define K_TOT         25
#define MAX_DEG       96          /* Poisson(16): observed max ~36; 96 is ultra-safe */
#define NODES_PER_BLK 64
#define HS_STRIDE     804         /* 800 + 4: (4*a_r + a_c) distinct mod 32 -> conflict-free A reads */
#define THREADS       512
#define NWARP         16

// Per-node cursors, bucketed 16B edge records (basis precomputed), tf32 weights.
__device__ int g_cnt[N_NODES];
__device__ __align__(16) float4 g_rec[(size_t)N_NODES * MAX_DEG];
__device__ __align__(16) uint32_t g_Wtf[K_TOT * 32 * OUT_F];   // [800][64] tf32

__device__ __forceinline__ uint32_t f2tf32(float f) {
    uint32_t r;
    asm("cvt.rna.tf32.f32 %0, %1;" : "=r"(r) : "f"(f));
    return r;
}

// ---------------------------------------------------------------------------
// Prep: zero per-node counters AND convert W to tf32 (one grid covers both).
__global__ void prep_kernel(const float* __restrict__ Wt) {
    int i = blockIdx.x * blockDim.x + threadIdx.x;
    if (i < N_NODES) g_cnt[i] = 0;
    if (i < K_TOT * 32 * OUT_F) g_Wtf[i] = f2tf32(Wt[i]);
}

// ---------------------------------------------------------------------------
// Bucket edges by destination node; precompute spline basis + kernel bin.
// rec = { col | bin<<17 , b00, b01, b10 }   (b11 = 1 - b00 - b01 - b10)
__global__ void bucket_kernel(const int* __restrict__ ei,
                              const float2* __restrict__ ps, int E) {
    int e = blockIdx.x * blockDim.x + threadIdx.x;
    if (e >= E) return;
    int row = ei[e];
    int col = ei[E + e];
    float2 p = ps[e];
    float v0 = p.x * 4.0f, v1 = p.y * 4.0f;
    int i0 = (int)v0; i0 = i0 < 0 ? 0 : (i0 > 3 ? 3 : i0);
    int i1 = (int)v1; i1 = i1 < 0 ? 0 : (i1 > 3 ? 3 : i1);
    float f0 = v0 - (float)i0, f1 = v1 - (float)i1;
    float g0 = 1.0f - f0,      g1 = 1.0f - f1;
    int bin = i0 * 5 + i1;
    uint32_t u = (uint32_t)col | ((uint32_t)bin << 17);
    int pos = atomicAdd(&g_cnt[row], 1);
    if (pos < MAX_DEG)
        g_rec[(size_t)row * MAX_DEG + pos] =
            make_float4(__uint_as_float(u), g0 * g1, g0 * f1, f0 * g1);
}

// ---------------------------------------------------------------------------
// Fused: smem accumulation of H tile (64 nodes x 800) + tf32 TC GEMM + bias.
__global__ void __launch_bounds__(THREADS)
fused_kernel(const float* __restrict__ feat,   // [N,32]
             const float* __restrict__ bias,   // [64]
             float*       __restrict__ out) {  // [N,64]
    extern __shared__ float sm[];
    float*    Hs = sm;                                           // 64 x 804
    uint32_t* Bs = (uint32_t*)(sm + NODES_PER_BLK * HS_STRIDE);  // 32 x 72 tf32

    const int tid   = threadIdx.x;
    const int lane  = tid & 31;
    const int warp  = tid >> 5;
    const int nbase = blockIdx.x * NODES_PER_BLK;

    // prefetch first W chunk (tf32) into registers; lands during accumulation
    uint4 wreg = ((const uint4*)g_Wtf)[tid];

    // --- zero H tile ---
    for (int i = tid; i < NODES_PER_BLK * HS_STRIDE / 4; i += THREADS)
        ((float4*)Hs)[i] = make_float4(0.f, 0.f, 0.f, 0.f);
    __syncthreads();

    // --- accumulation: warp w exclusively owns local nodes [w*4, w*4+4) ---
    for (int ln = warp * 4; ln < warp * 4 + 4; ln++) {
        int n = nbase + ln;
        if (n >= N_NODES) continue;
        int c = g_cnt[n];
        if (c > MAX_DEG) c = MAX_DEG;
        if (c == 0) continue;
        const float4* __restrict__ rec = &g_rec[(size_t)n * MAX_DEG];
        float* __restrict__ hrow = Hs + ln * HS_STRIDE;

        float4 rc[4];
        float  xv[4];
#pragma unroll
        for (int q = 0; q < 4; q++) rc[q] = rec[min(q, c - 1)];
#pragma unroll
        for (int q = 0; q < 4; q++) {
            int cq = (int)(__float_as_uint(rc[q].x) & 0x1FFFFu);
            xv[q] = feat[cq * IN_F + lane];
        }
        for (int base = 0; base < c; base += 4) {
            float4 rn[4];
            const int nb = base + 4;
            if (nb < c) {
#pragma unroll
                for (int q = 0; q < 4; q++) rn[q] = rec[min(nb + q, c - 1)];
            }
#pragma unroll
            for (int q = 0; q < 4; q++) {
                if (base + q < c) {
                    uint32_t u = __float_as_uint(rc[q].x);
                    int kb = (int)(u >> 17) * IN_F + lane;
                    float b00 = rc[q].y, b01 = rc[q].z, b10 = rc[q].w;
                    float b11 = 1.0f - b00 - b01 - b10;
                    float x = xv[q];
                    hrow[kb            ] += b00 * x;
                    hrow[kb +     IN_F ] += b01 * x;
                    hrow[kb + 5 * IN_F ] += b10 * x;
                    hrow[kb + 6 * IN_F ] += b11 * x;
                }
            }
            if (nb < c) {
#pragma unroll
                for (int q = 0; q < 4; q++) {
                    rc[q] = rn[q];
                    int cq = (int)(__float_as_uint(rc[q].x) & 0x1FFFFu);
                    xv[q] = feat[cq * IN_F + lane];
                }
            }
        }
    }
    __syncthreads();

    // --- tf32 TC GEMM: out[64,64] = Hs[64,800] @ W[800,64] + bias ---
    const int a_r    = lane >> 2;   // 0..7
    const int a_c    = lane & 3;    // 0..3
    const int stripe = warp & 3;    // 16-row stripe
    const int quar   = warp >> 2;   // 16-col quarter

    // B-staging indices: 512 uint4 = full 32x64 chunk, 1 per thread
    const int w_r  = tid >> 4;      // k-row 0..31
    const int w_c4 = tid & 15;      // uint4 col 0..15

    float acc[2][4];
#pragma unroll
    for (int j = 0; j < 2; j++)
#pragma unroll
        for (int q = 0; q < 4; q++) acc[j][q] = 0.f;

    for (int kc = 0; kc < K_TOT; kc++) {
        *(uint4*)(Bs + w_r * 72 + w_c4 * 4) = wreg;
        __syncthreads();
        if (kc + 1 < K_TOT)
            wreg = ((const uint4*)g_Wtf)[(kc + 1) * 512 + tid];  // overlaps mma

#pragma unroll
        for (int ks = 0; ks < 4; ks++) {
            const float* ab = Hs + (stripe * 16 + a_r) * HS_STRIDE + kc * 32 + ks * 8 + a_c;
            uint32_t a0 = f2tf32(ab[0]);
            uint32_t a1 = f2tf32(ab[8 * HS_STRIDE]);
            uint32_t a2 = f2tf32(ab[4]);
            uint32_t a3 = f2tf32(ab[8 * HS_STRIDE + 4]);
#pragma unroll
            for (int j = 0; j < 2; j++) {
                uint32_t b0 = Bs[(ks * 8 + a_c    ) * 72 + quar * 16 + j * 8 + a_r];
                uint32_t b1 = Bs[(ks * 8 + a_c + 4) * 72 + quar * 16 + j * 8 + a_r];
                asm volatile(
                    "mma.sync.aligned.m16n8k8.row.col.f32.tf32.tf32.f32 "
                    "{%0,%1,%2,%3}, {%4,%5,%6,%7}, {%8,%9}, {%0,%1,%2,%3};\n"
                    : "+f"(acc[j][0]), "+f"(acc[j][1]),
                      "+f"(acc[j][2]), "+f"(acc[j][3])
                    : "r"(a0), "r"(a1), "r"(a2), "r"(a3), "r"(b0), "r"(b1));
            }
        }
        __syncthreads();
    }

    // --- epilogue ---
    int r0 = nbase + stripe * 16 + a_r;
    int r1 = r0 + 8;
#pragma unroll
    for (int j = 0; j < 2; j++) {
        int c = quar * 16 + j * 8 + a_c * 2;
        float bv0 = bias[c], bv1 = bias[c + 1];
        if (r0 < N_NODES)
            *(float2*)(out + (size_t)r0 * OUT_F + c) =
                make_float2(acc[j][0] + bv0, acc[j][1] + bv1);
        if (r1 < N_NODES)
            *(float2*)(out + (size_t)r1 * OUT_F + c) =
                make_float2(acc[j][2] + bv0, acc[j][3] + bv1);
    }
}

// ---------------------------------------------------------------------------
extern "C" void kernel_launch(void* const* d_in, const int* in_sizes, int n_in,
                              void* d_out, int out_size) {
    const float*  feat   = (const float*) d_in[0];
    const float2* pseudo = (const float2*)d_in[1];
    const int*    ei     = (const int*)   d_in[2];
    const float*  Wt     = (const float*) d_in[3];
    const float*  bias   = (const float*) d_in[4];
    float*        out    = (float*)       d_out;

    const int E = in_sizes[1] / 2;

    const int smem_bytes = (NODES_PER_BLK * HS_STRIDE + 32 * 72) * 4;  // 215040
    cudaFuncSetAttribute(fused_kernel, cudaFuncAttributeMaxDynamicSharedMemorySize,
                         smem_bytes);

    prep_kernel<<<(N_NODES + 255) / 256, 256>>>(Wt);
    bucket_kernel<<<(E + 255) / 256, 256>>>(ei, pseudo, E);
    fused_kernel<<<(N_NODES + NODES_PER_BLK - 1) / NODES_PER_BLK, THREADS, smem_bytes>>>(
        feat, bias, out);
}

// round 4
// speedup vs baseline: 14.2304x; 1.1219x over previous
#include <cuda_runtime.h>
#include <cuda_fp16.h>
#include <cstdint>

#define N_NODES       100000
#define IN_F          32
#define OUT_F         64
#define K_TOT         25
#define MAX_DEG       96          /* Poisson(16): observed max ~36; 96 is ultra-safe */
#define NODES_PER_BLK 64
#define HS_STRIDE     804         /* floats; 804 % 32 == 4 -> conflict-free frag reads */
#define THREADS       512
#define BS_NSTRIDE    20          /* words per n-row of a staged B chunk; 20%32=20 -> CF */
#define BS_CHUNK      (64 * BS_NSTRIDE)   /* 1280 words = 5120 B per kc chunk */

// Per-node cursors, bucketed 16B edge records (basis precomputed), fp16 weights
// pre-packed in mma-fragment order: g_Whalf[kc][n][kword] (kword 0..15 data, 16..19 pad).
__device__ int g_cnt[N_NODES];
__device__ __align__(16) float4   g_rec[(size_t)N_NODES * MAX_DEG];
__device__ __align__(16) uint32_t g_Whalf[K_TOT * BS_CHUNK];

// ---------------------------------------------------------------------------
// Prep: zero per-node counters AND build fragment-ordered fp16 W.
__global__ void prep_kernel(const float* __restrict__ Wt) {
    int i = blockIdx.x * blockDim.x + threadIdx.x;
    if (i < N_NODES) g_cnt[i] = 0;
    if (i < K_TOT * BS_CHUNK) {
        int kc = i / BS_CHUNK;
        int r  = i % BS_CHUNK;
        int n  = r / BS_NSTRIDE;
        int kw = r % BS_NSTRIDE;
        uint32_t v = 0;
        if (kw < 16) {
            int k = kc * 32 + kw * 2;
            __half h0 = __float2half_rn(Wt[(size_t)k       * OUT_F + n]);
            __half h1 = __float2half_rn(Wt[(size_t)(k + 1) * OUT_F + n]);
            v = (uint32_t)__half_as_ushort(h0) |
                ((uint32_t)__half_as_ushort(h1) << 16);
        }
        g_Whalf[i] = v;
    }
}

// ---------------------------------------------------------------------------
// Bucket edges by destination node; precompute spline basis + kernel bin.
// rec = { col | bin<<17 , b00, b01, b10 }   (b11 = 1 - b00 - b01 - b10)
__global__ void bucket_kernel(const int* __restrict__ ei,
                              const float2* __restrict__ ps, int E) {
    int e = blockIdx.x * blockDim.x + threadIdx.x;
    if (e >= E) return;
    int row = ei[e];
    int col = ei[E + e];
    float2 p = ps[e];
    float v0 = p.x * 4.0f, v1 = p.y * 4.0f;
    int i0 = (int)v0; i0 = i0 < 0 ? 0 : (i0 > 3 ? 3 : i0);
    int i1 = (int)v1; i1 = i1 < 0 ? 0 : (i1 > 3 ? 3 : i1);
    float f0 = v0 - (float)i0, f1 = v1 - (float)i1;
    float g0 = 1.0f - f0,      g1 = 1.0f - f1;
    int bin = i0 * 5 + i1;
    uint32_t u = (uint32_t)col | ((uint32_t)bin << 17);
    int pos = atomicAdd(&g_cnt[row], 1);
    if (pos < MAX_DEG)
        g_rec[(size_t)row * MAX_DEG + pos] =
            make_float4(__uint_as_float(u), g0 * g1, g0 * f1, f0 * g1);
}

// ---------------------------------------------------------------------------
// Fused: smem fp32 accumulation of H tile (64 x 800) -> in-place fp16 pack
// -> fp16 tensor-core GEMM (m16n8k16) with double-buffered B staging.
__global__ void __launch_bounds__(THREADS)
fused_kernel(const float* __restrict__ feat,   // [N,32]
             const float* __restrict__ bias,   // [64]
             float*       __restrict__ out) {  // [N,64]
    extern __shared__ float sm[];
    float*    Hs  = sm;                                          // 64 x 804 fp32
    uint32_t* Bsm = (uint32_t*)(sm + NODES_PER_BLK * HS_STRIDE); // 2 x 1280 words

    const int tid   = threadIdx.x;
    const int lane  = tid & 31;
    const int warp  = tid >> 5;
    const int nbase = blockIdx.x * NODES_PER_BLK;

    // prefetch first W chunk; lands during accumulation
    uint4 wreg;
    if (tid < BS_CHUNK / 4)
        wreg = ((const uint4*)g_Whalf)[tid];

    // --- zero H tile ---
    for (int i = tid; i < NODES_PER_BLK * HS_STRIDE / 4; i += THREADS)
        ((float4*)Hs)[i] = make_float4(0.f, 0.f, 0.f, 0.f);
    __syncthreads();

    // --- accumulation: warp w exclusively owns local rows [w*4, w*4+4) ---
    for (int ln = warp * 4; ln < warp * 4 + 4; ln++) {
        int n = nbase + ln;
        if (n >= N_NODES) continue;
        int c = g_cnt[n];
        if (c > MAX_DEG) c = MAX_DEG;
        if (c == 0) continue;
        const float4* __restrict__ rec = &g_rec[(size_t)n * MAX_DEG];
        float* __restrict__ hrow = Hs + ln * HS_STRIDE;

        float4 rc[4];
        float  xv[4];
#pragma unroll
        for (int q = 0; q < 4; q++) rc[q] = rec[min(q, c - 1)];
#pragma unroll
        for (int q = 0; q < 4; q++) {
            int cq = (int)(__float_as_uint(rc[q].x) & 0x1FFFFu);
            xv[q] = feat[cq * IN_F + lane];
        }
        for (int base = 0; base < c; base += 4) {
            float4 rn[4];
            const int nb = base + 4;
            if (nb < c) {
#pragma unroll
                for (int q = 0; q < 4; q++) rn[q] = rec[min(nb + q, c - 1)];
            }
#pragma unroll
            for (int q = 0; q < 4; q++) {
                if (base + q < c) {
                    uint32_t u = __float_as_uint(rc[q].x);
                    int kb = (int)(u >> 17) * IN_F + lane;
                    float b00 = rc[q].y, b01 = rc[q].z, b10 = rc[q].w;
                    float b11 = 1.0f - b00 - b01 - b10;
                    float x = xv[q];
                    hrow[kb            ] += b00 * x;
                    hrow[kb +     IN_F ] += b01 * x;
                    hrow[kb + 5 * IN_F ] += b10 * x;
                    hrow[kb + 6 * IN_F ] += b11 * x;
                }
            }
            if (nb < c) {
#pragma unroll
                for (int q = 0; q < 4; q++) {
                    rc[q] = rn[q];
                    int cq = (int)(__float_as_uint(rc[q].x) & 0x1FFFFu);
                    xv[q] = feat[cq * IN_F + lane];
                }
            }
        }
    }

    // --- in-place fp16 pack of own rows (no inter-warp sync needed yet) ---
    for (int ln = warp * 4; ln < warp * 4 + 4; ln++) {
        float* hrow = Hs + ln * HS_STRIDE;
        float v[25];
#pragma unroll
        for (int r = 0; r < 25; r++) v[r] = hrow[r * 32 + lane];
        __syncwarp();
        __half* hp = (__half*)hrow;
#pragma unroll
        for (int r = 0; r < 25; r++) hp[r * 32 + lane] = __float2half_rn(v[r]);
    }

    // stage B chunk 0 into buffer 0
    if (tid < BS_CHUNK / 4)
        ((uint4*)Bsm)[tid] = wreg;
    __syncthreads();   // covers pack visibility + Bs0

    // --- fp16 TC GEMM: out[64,64] = H[64,800] @ W[800,64] + bias ---
    const int a_r    = lane >> 2;   // 0..7
    const int a_c    = lane & 3;    // 0..3
    const int stripe = warp & 3;    // 16-row stripe
    const int quar   = warp >> 2;   // 16-col quarter

    const uint32_t* arow0 = (const uint32_t*)Hs + (stripe * 16 + a_r) * HS_STRIDE;
    const uint32_t* arow1 = arow0 + 8 * HS_STRIDE;

    float acc[2][4];
#pragma unroll
    for (int j = 0; j < 2; j++)
#pragma unroll
        for (int q = 0; q < 4; q++) acc[j][q] = 0.f;

    for (int kc = 0; kc < K_TOT; kc++) {
        const uint32_t* Bcur = Bsm + (kc & 1) * BS_CHUNK;
        uint4 wnext;
        const bool more = (kc + 1 < K_TOT) && (tid < BS_CHUNK / 4);
        if (more)
            wnext = ((const uint4*)(g_Whalf + (kc + 1) * BS_CHUNK))[tid];

#pragma unroll
        for (int ks = 0; ks < 2; ks++) {
            int abase = kc * 16 + ks * 8 + a_c;
            uint32_t a0 = arow0[abase];
            uint32_t a1 = arow1[abase];
            uint32_t a2 = arow0[abase + 4];
            uint32_t a3 = arow1[abase + 4];
#pragma unroll
            for (int j = 0; j < 2; j++) {
                const uint32_t* bn = Bcur + (quar * 16 + j * 8 + a_r) * BS_NSTRIDE;
                uint32_t b0 = bn[ks * 8 + a_c];
                uint32_t b1 = bn[ks * 8 + a_c + 4];
                asm volatile(
                    "mma.sync.aligned.m16n8k16.row.col.f32.f16.f16.f32 "
                    "{%0,%1,%2,%3}, {%4,%5,%6,%7}, {%8,%9}, {%0,%1,%2,%3};\n"
                    : "+f"(acc[j][0]), "+f"(acc[j][1]),
                      "+f"(acc[j][2]), "+f"(acc[j][3])
                    : "r"(a0), "r"(a1), "r"(a2), "r"(a3), "r"(b0), "r"(b1));
            }
        }
        if (more)
            ((uint4*)(Bsm + ((kc + 1) & 1) * BS_CHUNK))[tid] = wnext;
        __syncthreads();
    }

    // --- epilogue ---
    int r0 = nbase + stripe * 16 + a_r;
    int r1 = r0 + 8;
#pragma unroll
    for (int j = 0; j < 2; j++) {
        int c = quar * 16 + j * 8 + a_c * 2;
        float bv0 = bias[c], bv1 = bias[c + 1];
        if (r0 < N_NODES)
            *(float2*)(out + (size_t)r0 * OUT_F + c) =
                make_float2(acc[j][0] + bv0, acc[j][1] + bv1);
        if (r1 < N_NODES)
            *(float2*)(out + (size_t)r1 * OUT_F + c) =
                make_float2(acc[j][2] + bv0, acc[j][3] + bv1);
    }
}

// ---------------------------------------------------------------------------
extern "C" void kernel_launch(void* const* d_in, const int* in_sizes, int n_in,
                              void* d_out, int out_size) {
    const float*  feat   = (const float*) d_in[0];
    const float2* pseudo = (const float2*)d_in[1];
    const int*    ei     = (const int*)   d_in[2];
    const float*  Wt     = (const float*) d_in[3];
    const float*  bias   = (const float*) d_in[4];
    float*        out    = (float*)       d_out;

    const int E = in_sizes[1] / 2;

    const int smem_bytes = NODES_PER_BLK * HS_STRIDE * 4 + 2 * BS_CHUNK * 4; // 216064
    cudaFuncSetAttribute(fused_kernel, cudaFuncAttributeMaxDynamicSharedMemorySize,
                         smem_bytes);

    prep_kernel<<<(N_NODES + 255) / 256, 256>>>(Wt);
    bucket_kernel<<<(E + 255) / 256, 256>>>(ei, pseudo, E);
    fused_kernel<<<(N_NODES + NODES_PER_BLK - 1) / NODES_PER_BLK, THREADS, smem_bytes>>>(
        feat, bias, out);
}